// round 11
// baseline (speedup 1.0000x reference)
#include <cuda_runtime.h>

#define NEG (-1e30f)
#define LOG2E 1.4426950408889634f
#define LN2   0.6931471805599453f

constexpr int B  = 8;
constexpr int T  = 200;
constexpr int U1 = 101;
constexpr int V  = 512;
constexpr int U  = U1 - 1;
constexpr int D  = T + U1 - 1;           // 300 anti-diagonals
constexpr int NCELL = B * T * U1;        // 161600
constexpr int SU = 101;                  // skew row stride (cols 0..100)
constexpr int K  = 5;                    // diagonals per superstep

// Skewed log2-prob tables: [b][d = t+u][u]  (pre-scaled by log2 e)
__device__ float g_bsk[B * D * SU];
__device__ float g_esk[B * D * SU];
__device__ int   g_dctr[B * D];          // per-(batch, diagonal) completion counters
__device__ float g_loss[B];
__device__ int   g_ctr;

__device__ __forceinline__ float ex2_(float x) {
    float r; asm("ex2.approx.ftz.f32 %0, %1;" : "=f"(r) : "f"(x)); return r;
}
__device__ __forceinline__ float lg2_(float x) {
    float r; asm("lg2.approx.ftz.f32 %0, %1;" : "=f"(r) : "f"(x)); return r;
}
__device__ __forceinline__ float laddexp2(float a, float b) {
    float mx = fmaxf(a, b);
    float dd = -fabsf(a - b);
    return mx + lg2_(1.0f + ex2_(dd));
}

__global__ void k_init() {
    for (int i = threadIdx.x; i < B * D; i += 256) g_dctr[i] = 0;
    if (threadIdx.x == 0) g_ctr = 0;
}

// ---------------- LSE producer role ----------------
// One warp per (b,t,u) live cell, t-major ordering so diagonals complete in
// DP consumption order. Publishes per-(b,diag) counters with release semantics.
__device__ __forceinline__ void lse_role(int lseb,
                                         const float* __restrict__ logits,
                                         const int*   __restrict__ targets,
                                         const int*   __restrict__ fbank_len,
                                         const int*   __restrict__ text_len) {
    int gw   = lseb * 8 + (threadIdx.x >> 5);
    int lane = threadIdx.x & 31;
    if (gw >= NCELL) return;

    // t-major decode: gw = (t*U1 + u)*B + b
    int b   = gw % B;
    int rem = gw / B;
    int u   = rem % U1;
    int t   = rem / U1;

    int lab_len = text_len[b] - 1;
    if (t >= fbank_len[b] || u > lab_len) return;   // dead cell: skip, not counted

    size_t row = ((size_t)(b * T + t) * U1 + u);
    const float4* p = reinterpret_cast<const float4*>(logits) + row * (V / 4);
    float4 v0 = p[lane];
    float4 v1 = p[lane + 32];
    float4 v2 = p[lane + 64];
    float4 v3 = p[lane + 96];

    float m = fmaxf(fmaxf(fmaxf(v0.x, v0.y), fmaxf(v0.z, v0.w)),
                    fmaxf(fmaxf(fmaxf(v1.x, v1.y), fmaxf(v1.z, v1.w)),
                          fmaxf(fmaxf(fmaxf(v2.x, v2.y), fmaxf(v2.z, v2.w)),
                                fmaxf(fmaxf(v3.x, v3.y), fmaxf(v3.z, v3.w)))));
#pragma unroll
    for (int o = 16; o; o >>= 1) m = fmaxf(m, __shfl_xor_sync(0xffffffffu, m, o));

    float s = __expf(v0.x - m) + __expf(v0.y - m) + __expf(v0.z - m) + __expf(v0.w - m)
            + __expf(v1.x - m) + __expf(v1.y - m) + __expf(v1.z - m) + __expf(v1.w - m)
            + __expf(v2.x - m) + __expf(v2.y - m) + __expf(v2.z - m) + __expf(v2.w - m)
            + __expf(v3.x - m) + __expf(v3.y - m) + __expf(v3.z - m) + __expf(v3.w - m);
#pragma unroll
    for (int o = 16; o; o >>= 1) s += __shfl_xor_sync(0xffffffffu, s, o);

    float lse = m + __logf(s);

    int d = t + u;
    size_t base = ((size_t)b * D + d) * SU + u;
    if (lane == 0) g_bsk[base] = (v0.x - lse) * LOG2E;

    int lab = (u < U) ? targets[b * U1 + u + 1] : -1;
    if (lab >= 0) {
        int chunk = lab >> 2;
        if ((chunk & 31) == lane) {
            int j = chunk >> 5, c = lab & 3;
            float4 vv = (j == 0) ? v0 : (j == 1) ? v1 : (j == 2) ? v2 : v3;
            float ev  = (c == 0) ? vv.x : (c == 1) ? vv.y : (c == 2) ? vv.z : vv.w;
            g_esk[base] = (ev - lse) * LOG2E;
        }
    }

    // release: all lanes fence (covers both storing lanes), then one atomic
    __threadfence();
    __syncwarp();
    if (lane == 0) atomicAdd(&g_dctr[b * D + d], 1);
}

// ---------------- DP consumer role ----------------
// Block b: warps 0-3 (128 thr, named barrier) run the K-blocked triangle DP
// reading skewed tables via __ldcg; warp 7 thread walks the counters and
// publishes a monotone frontier in smem.
__device__ __forceinline__ void dp_role(int b,
                                        const int* __restrict__ fbank_len,
                                        const int* __restrict__ text_len,
                                        float* __restrict__ out) {
    __shared__ int s_frontier;
    __shared__ float A[2][128 + K + 1];

    int tid = threadIdx.x;
    int u   = tid;

    int lab_len = text_len[b] - 1;
    int tfin    = fbank_len[b] - 1;
    int dfin    = tfin + lab_len;

    if (tid == 0) *(volatile int*)&s_frontier = -1;
    __syncthreads();                     // all 256 threads, once

    // waiter: walks diagonals 0..dfin, spins on per-diagonal counters
    if (tid >= 128) {
        if (tid == 224) {
            volatile int* ctr = (volatile int*)(g_dctr + b * D);
            for (int dd = 0; dd <= dfin; ++dd) {
                int lo  = max(0, dd - tfin);
                int hi  = min(dd, lab_len);
                int cnt = hi - lo + 1;   // >= 1 for dd <= dfin
                while (ctr[dd] < cnt) __nanosleep(64);
                *(volatile int*)&s_frontier = dd;
            }
        }
        return;
    }

    const float* bsk = g_bsk + (size_t)b * D * SU;
    const float* esk = g_esk + (size_t)b * D * SU;

    if (tid < K) { A[0][tid] = NEG; A[1][tid] = NEG; }   // left pad
    A[0][u + K] = (u == 0) ? 0.0f : NEG;                 // diagonal 0
    asm volatile("bar.sync 1, 128;" ::: "memory");

    bool fin   = (u == lab_len);
    float afin = NEG;

    int buf = 0;
    for (int d0 = 0; d0 < dfin; d0 += K) {
        int need = min(d0 + K - 1, dfin);
        while (*(volatile int*)&s_frontier < need) { }   // cheap smem spin

        float bb[K + 1];
#pragma unroll
        for (int j = 0; j <= K; ++j) bb[j] = A[buf][u - j + K];

        // per-row double-buffered table loads (coalesced L2 via skew layout)
        float tb[2][K], te[2][K];
#pragma unroll
        for (int j = 0; j < K; ++j) {                    // row i=1
            int up = u - j, t = d0 + 1 - up;
            bool vs = (up >= 0 && up < U1 && t >= 1 && t < T);
            bool vm = (up >= 1 && up < U1 && t >= 0 && t < T);
            tb[0][j] = vs ? __ldcg(bsk + d0 * SU + up)     : NEG;
            te[0][j] = vm ? __ldcg(esk + d0 * SU + up - 1) : NEG;
        }
        int pb = 0;
#pragma unroll
        for (int i = 1; i <= K; ++i) {
            if (i < K) {                                 // prefetch row i+1
#pragma unroll
                for (int j = 0; j <= K - i - 1; ++j) {
                    int up = u - j, t = d0 + i + 1 - up;
                    bool vs = (up >= 0 && up < U1 && t >= 1 && t < T);
                    bool vm = (up >= 1 && up < U1 && t >= 0 && t < T);
                    tb[pb ^ 1][j] = vs ? __ldcg(bsk + (d0 + i) * SU + up)     : NEG;
                    te[pb ^ 1][j] = vm ? __ldcg(esk + (d0 + i) * SU + up - 1) : NEG;
                }
            }
#pragma unroll
            for (int j = 0; j <= K - i; ++j)
                bb[j] = laddexp2(bb[j] + tb[pb][j], bb[j + 1] + te[pb][j]);
            if (fin && (d0 + i) == dfin) afin = bb[0];
            pb ^= 1;
        }

        A[buf ^ 1][u + K] = bb[0];
        asm volatile("bar.sync 1, 128;" ::: "memory");
        buf ^= 1;
    }

    if (fin) {
        while (*(volatile int*)&s_frontier < dfin) { }
        float bl = __ldcg(bsk + dfin * SU + lab_len);
        g_loss[b] = -LN2 * (afin + bl);
        __threadfence();
        int done = atomicAdd(&g_ctr, 1);
        if (done == B - 1) {
            __threadfence();
            float s = 0.0f;
#pragma unroll
            for (int i = 0; i < B; ++i) s += *((volatile float*)&g_loss[i]);
            out[0] = s / (float)B;
        }
    }
}

// ---------------- fused kernel ----------------
__global__ void __launch_bounds__(256) k_fused(const float* __restrict__ logits,
                                               const int*   __restrict__ targets,
                                               const int*   __restrict__ fbank_len,
                                               const int*   __restrict__ text_len,
                                               float* __restrict__ out) {
    if (blockIdx.x < B) {
        dp_role(blockIdx.x, fbank_len, text_len, out);
    } else {
        lse_role(blockIdx.x - B, logits, targets, fbank_len, text_len);
    }
}

extern "C" void kernel_launch(void* const* d_in, const int* in_sizes, int n_in,
                              void* d_out, int out_size) {
    const float* logits  = (const float*)d_in[0];
    const int*   targets = (const int*)d_in[1];
    const int*   fb      = (const int*)d_in[2];
    const int*   tl      = (const int*)d_in[3];

    int lse_blocks = NCELL / 8;              // 20200 (exact)
    k_init<<<1, 256>>>();
    k_fused<<<B + lse_blocks, 256>>>(logits, targets, fb, tl, (float*)d_out);
}

// round 12
// speedup vs baseline: 1.0223x; 1.0223x over previous
#include <cuda_runtime.h>

#define NEG (-1e30f)
#define LOG2E 1.4426950408889634f
#define LN2   0.6931471805599453f

constexpr int B  = 8;
constexpr int T  = 200;
constexpr int U1 = 101;
constexpr int V  = 512;
constexpr int U  = U1 - 1;
constexpr int D  = T + U1 - 1;           // 300 anti-diagonals
constexpr int NCELL = B * T * U1;        // 161600
constexpr int SU = 101;                  // skew row stride (cols 0..100)
constexpr int K  = 5;                    // diagonals per superstep

// Skewed log2-prob tables: [b][d = t+u][u]  (pre-scaled by log2 e)
__device__ float g_bsk[B * D * SU];
__device__ float g_esk[B * D * SU];
__device__ int   g_dctr[B * D];          // per-(batch, diagonal) completion counters
__device__ float g_loss[B];
__device__ int   g_ctr;

__device__ __forceinline__ float ex2_(float x) {
    float r; asm("ex2.approx.ftz.f32 %0, %1;" : "=f"(r) : "f"(x)); return r;
}
__device__ __forceinline__ float lg2_(float x) {
    float r; asm("lg2.approx.ftz.f32 %0, %1;" : "=f"(r) : "f"(x)); return r;
}
__device__ __forceinline__ float laddexp2(float a, float b) {
    float mx = fmaxf(a, b);
    float dd = -fabsf(a - b);
    return mx + lg2_(1.0f + ex2_(dd));
}

__global__ void k_init() {
    for (int i = threadIdx.x; i < B * D; i += 256) g_dctr[i] = 0;
    if (threadIdx.x == 0) g_ctr = 0;
}

// ---------------- LSE producer role ----------------
// One warp per (b,t,u) cell. Ordering: gw = (t*B + b)*U1 + u  — u innermost,
// so consecutive warps read CONSECUTIVE 2KB logit rows (DRAM streaming),
// while t ascends over blocks so DP diagonals complete in order.
__device__ __forceinline__ void lse_role(int lseb,
                                         const float* __restrict__ logits,
                                         const int*   __restrict__ targets,
                                         const int*   __restrict__ fbank_len,
                                         const int*   __restrict__ text_len) {
    int gw   = lseb * 8 + (threadIdx.x >> 5);
    int lane = threadIdx.x & 31;
    if (gw >= NCELL) return;

    int u   = gw % U1;
    int rem = gw / U1;
    int b   = rem % B;
    int t   = rem / B;

    int lab_len = text_len[b] - 1;
    if (t >= fbank_len[b] || u > lab_len) return;   // dead cell: skip, not counted

    size_t row = ((size_t)(b * T + t) * U1 + u);
    const float4* p = reinterpret_cast<const float4*>(logits) + row * (V / 4);
    float4 v0 = p[lane];
    float4 v1 = p[lane + 32];
    float4 v2 = p[lane + 64];
    float4 v3 = p[lane + 96];

    float m = fmaxf(fmaxf(fmaxf(v0.x, v0.y), fmaxf(v0.z, v0.w)),
                    fmaxf(fmaxf(fmaxf(v1.x, v1.y), fmaxf(v1.z, v1.w)),
                          fmaxf(fmaxf(fmaxf(v2.x, v2.y), fmaxf(v2.z, v2.w)),
                                fmaxf(fmaxf(v3.x, v3.y), fmaxf(v3.z, v3.w)))));
#pragma unroll
    for (int o = 16; o; o >>= 1) m = fmaxf(m, __shfl_xor_sync(0xffffffffu, m, o));

    float s = __expf(v0.x - m) + __expf(v0.y - m) + __expf(v0.z - m) + __expf(v0.w - m)
            + __expf(v1.x - m) + __expf(v1.y - m) + __expf(v1.z - m) + __expf(v1.w - m)
            + __expf(v2.x - m) + __expf(v2.y - m) + __expf(v2.z - m) + __expf(v2.w - m)
            + __expf(v3.x - m) + __expf(v3.y - m) + __expf(v3.z - m) + __expf(v3.w - m);
#pragma unroll
    for (int o = 16; o; o >>= 1) s += __shfl_xor_sync(0xffffffffu, s, o);

    float lse = m + __logf(s);

    int d = t + u;
    size_t base = ((size_t)b * D + d) * SU + u;
    if (lane == 0) g_bsk[base] = (v0.x - lse) * LOG2E;

    int lab = (u < U) ? targets[b * U1 + u + 1] : -1;
    if (lab >= 0) {
        int chunk = lab >> 2;
        if ((chunk & 31) == lane) {
            int j = chunk >> 5, c = lab & 3;
            float4 vv = (j == 0) ? v0 : (j == 1) ? v1 : (j == 2) ? v2 : v3;
            float ev  = (c == 0) ? vv.x : (c == 1) ? vv.y : (c == 2) ? vv.z : vv.w;
            g_esk[base] = (ev - lse) * LOG2E;
        }
    }

    // release: fence all lanes (covers both storing lanes), then one atomic
    __threadfence();
    __syncwarp();
    if (lane == 0) atomicAdd(&g_dctr[b * D + d], 1);
}

// ---------------- DP consumer role ----------------
// Block b: warps 0-3 (128 thr, named barrier) run the K-blocked triangle DP
// on skewed tables via __ldcg; one waiter thread walks per-diagonal counters
// and publishes a monotone smem frontier.
__device__ __forceinline__ void dp_role(int b,
                                        const int* __restrict__ fbank_len,
                                        const int* __restrict__ text_len,
                                        float* __restrict__ out) {
    __shared__ int s_frontier;
    __shared__ float A[2][128 + K + 1];

    int tid = threadIdx.x;
    int u   = tid;

    int lab_len = text_len[b] - 1;
    int tfin    = fbank_len[b] - 1;
    int dfin    = tfin + lab_len;

    if (tid == 0) *(volatile int*)&s_frontier = -1;
    __syncthreads();                     // all 256 threads, once

    // waiter: walks diagonals 0..dfin, spins on per-diagonal counters
    if (tid >= 128) {
        if (tid == 224) {
            volatile int* ctr = (volatile int*)(g_dctr + b * D);
            for (int dd = 0; dd <= dfin; ++dd) {
                int lo  = max(0, dd - tfin);
                int hi  = min(dd, lab_len);
                int cnt = hi - lo + 1;   // >= 1 for dd <= dfin
                while (ctr[dd] < cnt) __nanosleep(64);
                *(volatile int*)&s_frontier = dd;
            }
        }
        return;
    }

    const float* bsk = g_bsk + (size_t)b * D * SU;
    const float* esk = g_esk + (size_t)b * D * SU;

    if (tid < K) { A[0][tid] = NEG; A[1][tid] = NEG; }   // left pad
    A[0][u + K] = (u == 0) ? 0.0f : NEG;                 // diagonal 0
    asm volatile("bar.sync 1, 128;" ::: "memory");

    bool fin   = (u == lab_len);
    float afin = NEG;

    int buf = 0;
    for (int d0 = 0; d0 < dfin; d0 += K) {
        int need = min(d0 + K - 1, dfin);
        while (*(volatile int*)&s_frontier < need) __nanosleep(32);

        float bb[K + 1];
#pragma unroll
        for (int j = 0; j <= K; ++j) bb[j] = A[buf][u - j + K];

        // per-row double-buffered table loads (coalesced L2 via skew layout)
        float tb[2][K], te[2][K];
#pragma unroll
        for (int j = 0; j < K; ++j) {                    // row i=1
            int up = u - j, t = d0 + 1 - up;
            bool vs = (up >= 0 && up < U1 && t >= 1 && t < T);
            bool vm = (up >= 1 && up < U1 && t >= 0 && t < T);
            tb[0][j] = vs ? __ldcg(bsk + d0 * SU + up)     : NEG;
            te[0][j] = vm ? __ldcg(esk + d0 * SU + up - 1) : NEG;
        }
        int pb = 0;
#pragma unroll
        for (int i = 1; i <= K; ++i) {
            if (i < K) {                                 // prefetch row i+1
#pragma unroll
                for (int j = 0; j <= K - i - 1; ++j) {
                    int up = u - j, t = d0 + i + 1 - up;
                    bool vs = (up >= 0 && up < U1 && t >= 1 && t < T);
                    bool vm = (up >= 1 && up < U1 && t >= 0 && t < T);
                    tb[pb ^ 1][j] = vs ? __ldcg(bsk + (d0 + i) * SU + up)     : NEG;
                    te[pb ^ 1][j] = vm ? __ldcg(esk + (d0 + i) * SU + up - 1) : NEG;
                }
            }
#pragma unroll
            for (int j = 0; j <= K - i; ++j)
                bb[j] = laddexp2(bb[j] + tb[pb][j], bb[j + 1] + te[pb][j]);
            if (fin && (d0 + i) == dfin) afin = bb[0];
            pb ^= 1;
        }

        A[buf ^ 1][u + K] = bb[0];
        asm volatile("bar.sync 1, 128;" ::: "memory");
        buf ^= 1;
    }

    if (fin) {
        while (*(volatile int*)&s_frontier < dfin) __nanosleep(32);
        float bl = __ldcg(bsk + dfin * SU + lab_len);
        g_loss[b] = -LN2 * (afin + bl);
        __threadfence();
        int done = atomicAdd(&g_ctr, 1);
        if (done == B - 1) {
            __threadfence();
            float s = 0.0f;
#pragma unroll
            for (int i = 0; i < B; ++i) s += *((volatile float*)&g_loss[i]);
            out[0] = s / (float)B;
        }
    }
}

// ---------------- fused kernel ----------------
__global__ void __launch_bounds__(256) k_fused(const float* __restrict__ logits,
                                               const int*   __restrict__ targets,
                                               const int*   __restrict__ fbank_len,
                                               const int*   __restrict__ text_len,
                                               float* __restrict__ out) {
    if (blockIdx.x < B) {
        dp_role(blockIdx.x, fbank_len, text_len, out);
    } else {
        lse_role(blockIdx.x - B, logits, targets, fbank_len, text_len);
    }
}

extern "C" void kernel_launch(void* const* d_in, const int* in_sizes, int n_in,
                              void* d_out, int out_size) {
    const float* logits  = (const float*)d_in[0];
    const int*   targets = (const int*)d_in[1];
    const int*   fb      = (const int*)d_in[2];
    const int*   tl      = (const int*)d_in[3];

    int lse_blocks = NCELL / 8;              // 20200 (exact)
    k_init<<<1, 256>>>();
    k_fused<<<B + lse_blocks, 256>>>(logits, targets, fb, tl, (float*)d_out);
}

// round 13
// speedup vs baseline: 1.6916x; 1.6547x over previous
#include <cuda_runtime.h>

#define NEG (-1e30f)
#define LOG2E 1.4426950408889634f
#define LN2   0.6931471805599453f

constexpr int B  = 8;
constexpr int T  = 200;
constexpr int U1 = 101;
constexpr int V  = 512;
constexpr int U  = U1 - 1;
constexpr int D  = T + U1 - 1;           // 300 anti-diagonals
constexpr int NCELL = B * T * U1;
constexpr int SB = 102;                  // padded row stride (conflict-free anti-diagonal reads)
constexpr int K  = 5;                    // diagonals per barrier
constexpr int NTRI = K * (K + 1) / 2;    // 15 triangle cells

// Padded log2-prob tables: [b][t*SB + u]  (pre-scaled by log2 e)
__device__ float g_blank[B * T * SB];
__device__ float g_emit [B * T * SB];
__device__ float g_loss [B];
__device__ int   g_ctr;

__device__ __forceinline__ float ex2_(float x) {
    float r; asm("ex2.approx.ftz.f32 %0, %1;" : "=f"(r) : "f"(x)); return r;
}
__device__ __forceinline__ float lg2_(float x) {
    float r; asm("lg2.approx.ftz.f32 %0, %1;" : "=f"(r) : "f"(x)); return r;
}
__device__ __forceinline__ float laddexp2(float a, float b) {
    float mx = fmaxf(a, b);
    float dd = -fabsf(a - b);
    return mx + lg2_(1.0f + ex2_(dd));
}

// One warp per (b,t,u) cell: logsumexp over V=512; dead cells skipped.
// Logits are read-once -> __ldcs (evict-first) to keep them out of L2.
__global__ void __launch_bounds__(256) k_lse(const float* __restrict__ logits,
                                             const int*   __restrict__ targets,
                                             const int*   __restrict__ fbank_len,
                                             const int*   __restrict__ text_len) {
    int gw   = (blockIdx.x * blockDim.x + threadIdx.x) >> 5;
    int lane = threadIdx.x & 31;
    if (gw >= NCELL) return;

    int u = gw % U1;
    int t = (gw / U1) % T;
    int b = gw / (U1 * T);

    int lab_len = text_len[b] - 1;
    if (t >= fbank_len[b] || u > lab_len) return;   // never consumed by the DP

    const float4* p = reinterpret_cast<const float4*>(logits) + (size_t)gw * (V / 4);
    float4 v0 = __ldcs(p + lane);
    float4 v1 = __ldcs(p + lane + 32);
    float4 v2 = __ldcs(p + lane + 64);
    float4 v3 = __ldcs(p + lane + 96);

    float m = fmaxf(fmaxf(fmaxf(v0.x, v0.y), fmaxf(v0.z, v0.w)),
                    fmaxf(fmaxf(fmaxf(v1.x, v1.y), fmaxf(v1.z, v1.w)),
                          fmaxf(fmaxf(fmaxf(v2.x, v2.y), fmaxf(v2.z, v2.w)),
                                fmaxf(fmaxf(v3.x, v3.y), fmaxf(v3.z, v3.w)))));
#pragma unroll
    for (int o = 16; o; o >>= 1) m = fmaxf(m, __shfl_xor_sync(0xffffffffu, m, o));

    float s = __expf(v0.x - m) + __expf(v0.y - m) + __expf(v0.z - m) + __expf(v0.w - m)
            + __expf(v1.x - m) + __expf(v1.y - m) + __expf(v1.z - m) + __expf(v1.w - m)
            + __expf(v2.x - m) + __expf(v2.y - m) + __expf(v2.z - m) + __expf(v2.w - m)
            + __expf(v3.x - m) + __expf(v3.y - m) + __expf(v3.z - m) + __expf(v3.w - m);
#pragma unroll
    for (int o = 16; o; o >>= 1) s += __shfl_xor_sync(0xffffffffu, s, o);

    float lse = m + __logf(s);

    size_t base = (size_t)b * T * SB + t * SB + u;
    if (lane == 0) g_blank[base] = (v0.x - lse) * LOG2E;

    int lab = (u < U) ? targets[b * U1 + u + 1] : -1;
    if (lab >= 0) {
        int chunk = lab >> 2;
        if ((chunk & 31) == lane) {
            int j = chunk >> 5, c = lab & 3;
            float4 vv = (j == 0) ? v0 : (j == 1) ? v1 : (j == 2) ? v2 : v3;
            float ev  = (c == 0) ? vv.x : (c == 1) ? vv.y : (c == 2) ? vv.z : vv.w;
            g_emit[base] = (ev - lse) * LOG2E;
        }
    }
}

// ---- K-diagonal-blocked DP helpers (register-array refs, force-inlined) ----
__device__ __forceinline__ void tri_load(const float* __restrict__ smb,
                                         const float* __restrict__ sme,
                                         int u, int d0,
                                         float (&tb)[NTRI], float (&te)[NTRI]) {
    int idx = 0;
#pragma unroll
    for (int i = 1; i <= K; ++i) {
#pragma unroll
        for (int j = 0; j <= K - i; ++j, ++idx) {
            int up = u - j;
            int t  = d0 + i - up;
            bool vs = (t >= 1 && t < T && up >= 0 && up < U1);
            bool vm = (t >= 0 && t < T && up >= 1 && up < U1);
            tb[idx] = vs ? smb[(t - 1) * SB + up] : NEG;
            te[idx] = vm ? sme[t * SB + (up - 1)] : NEG;
        }
    }
}

__device__ __forceinline__ void tri_chain(float (&bb)[K + 1],
                                          const float (&tb)[NTRI], const float (&te)[NTRI],
                                          int d0, int dfin, bool fin, float& afin) {
    int idx = 0;
#pragma unroll
    for (int i = 1; i <= K; ++i) {
#pragma unroll
        for (int j = 0; j <= K - i; ++j, ++idx)
            bb[j] = laddexp2(bb[j] + tb[idx], bb[j + 1] + te[idx]);
        if (fin && (d0 + i) == dfin) afin = bb[0];
    }
}

// K-diagonal-blocked alpha DP, software-pipelined across supersteps:
// next superstep's 30 table loads are issued right after the alpha-row read
// and complete UNDER the current logaddexp chain (ping-pong register sets).
constexpr int SMEM_DP = 2 * T * SB * (int)sizeof(float);

__global__ void __launch_bounds__(128, 1) k_dp(const int* __restrict__ fbank_len,
                                               const int* __restrict__ text_len,
                                               float* __restrict__ out) {
    extern __shared__ float sm[];
    float* smb = sm;                     // blank [T][SB]
    float* sme = sm + T * SB;            // emit  [T][SB]
    __shared__ float A[2][128 + K + 1];  // alpha on base diagonal, double-buffered

    int b   = blockIdx.x;
    int tid = threadIdx.x;
    int u   = tid;

    {   // Stage tables (L2-resident, float4, layout matches padded gmem)
        const float4* gb4 = reinterpret_cast<const float4*>(g_blank + (size_t)b * T * SB);
        const float4* ge4 = reinterpret_cast<const float4*>(g_emit  + (size_t)b * T * SB);
        float4* sb4 = reinterpret_cast<float4*>(smb);
        float4* se4 = reinterpret_cast<float4*>(sme);
        for (int i = tid; i < T * SB / 4; i += 128) { sb4[i] = gb4[i]; se4[i] = ge4[i]; }
    }

    if (tid < K) { A[0][tid] = NEG; A[1][tid] = NEG; }
    A[0][u + K] = (u == 0) ? 0.0f : NEG;

    int lab_len = text_len[b] - 1;
    int tfin    = fbank_len[b] - 1;
    int dfin    = tfin + lab_len;
    bool fin    = (u == lab_len);
    float afin  = NEG;
    __syncthreads();

    float tbA[NTRI], teA[NTRI], tbB[NTRI], teB[NTRI];
    tri_load(smb, sme, u, 0, tbA, teA);         // prologue: superstep 0 tables

    int buf = 0;
    int d0  = 0;
    while (d0 < dfin) {
        {   // superstep using set A, prefetch into set B
            float bb[K + 1];
#pragma unroll
            for (int j = 0; j <= K; ++j) bb[j] = A[buf][u - j + K];
            if (d0 + K < dfin) tri_load(smb, sme, u, d0 + K, tbB, teB);
            tri_chain(bb, tbA, teA, d0, dfin, fin, afin);
            A[buf ^ 1][u + K] = bb[0];
            __syncthreads();
            buf ^= 1;
        }
        d0 += K;
        if (d0 >= dfin) break;
        {   // superstep using set B, prefetch into set A
            float bb[K + 1];
#pragma unroll
            for (int j = 0; j <= K; ++j) bb[j] = A[buf][u - j + K];
            if (d0 + K < dfin) tri_load(smb, sme, u, d0 + K, tbA, teA);
            tri_chain(bb, tbB, teB, d0, dfin, fin, afin);
            A[buf ^ 1][u + K] = bb[0];
            __syncthreads();
            buf ^= 1;
        }
        d0 += K;
    }

    // Per-batch loss + fused mean via last-CTA reduction
    if (fin) {
        g_loss[b] = -LN2 * (afin + smb[tfin * SB + lab_len]);
        __threadfence();
        int done = atomicAdd(&g_ctr, 1);
        if (done == B - 1) {
            __threadfence();
            float s = 0.0f;
#pragma unroll
            for (int i = 0; i < B; ++i) s += *((volatile float*)&g_loss[i]);
            out[0] = s / (float)B;
            g_ctr = 0;                    // reset for next graph replay
        }
    }
}

extern "C" void kernel_launch(void* const* d_in, const int* in_sizes, int n_in,
                              void* d_out, int out_size) {
    const float* logits  = (const float*)d_in[0];
    const int*   targets = (const int*)d_in[1];
    const int*   fb      = (const int*)d_in[2];
    const int*   tl      = (const int*)d_in[3];

    cudaFuncSetAttribute(k_dp, cudaFuncAttributeMaxDynamicSharedMemorySize, SMEM_DP);

    int blocks = (NCELL * 32 + 255) / 256;  // one warp per cell
    k_lse<<<blocks, 256>>>(logits, targets, fb, tl);
    k_dp<<<B, 128, SMEM_DP>>>(fb, tl, (float*)d_out);
}